// round 3
// baseline (speedup 1.0000x reference)
#include <cuda_runtime.h>
#include <cuda_bf16.h>

#define NN 8192
#define INF_DIM 512
#define OUTF 64
#define ALPHA 0.2f

// scratch (no cudaMalloc allowed)
__device__ float g_h[NN * OUTF];    // h = X @ W
__device__ float g_fs[NN];          // f_src
__device__ float g_fd[NN];          // f_dst

// ---------------------------------------------------------------------------
// Kernel A: h = X @ W.  16 rows / block, 256 threads.
// thread: c = tid%64 (output col), group g = tid/64 handles 4 rows.
// ---------------------------------------------------------------------------
__global__ void __launch_bounds__(256) gemm_h_kernel(const float* __restrict__ X,
                                                     const float* __restrict__ W) {
    int c = threadIdx.x & 63;
    int g = threadIdx.x >> 6;
    int row0 = blockIdx.x * 16 + g * 4;

    float acc0 = 0.f, acc1 = 0.f, acc2 = 0.f, acc3 = 0.f;
    const float* x0 = X + (size_t)(row0 + 0) * INF_DIM;
    const float* x1 = X + (size_t)(row0 + 1) * INF_DIM;
    const float* x2 = X + (size_t)(row0 + 2) * INF_DIM;
    const float* x3 = X + (size_t)(row0 + 3) * INF_DIM;

    #pragma unroll 4
    for (int k = 0; k < INF_DIM; k += 4) {
        float w0 = W[(k + 0) * OUTF + c];
        float w1 = W[(k + 1) * OUTF + c];
        float w2 = W[(k + 2) * OUTF + c];
        float w3 = W[(k + 3) * OUTF + c];
        float4 a = *(const float4*)(x0 + k);
        float4 b = *(const float4*)(x1 + k);
        float4 d = *(const float4*)(x2 + k);
        float4 e = *(const float4*)(x3 + k);
        acc0 += a.x * w0 + a.y * w1 + a.z * w2 + a.w * w3;
        acc1 += b.x * w0 + b.y * w1 + b.z * w2 + b.w * w3;
        acc2 += d.x * w0 + d.y * w1 + d.z * w2 + d.w * w3;
        acc3 += e.x * w0 + e.y * w1 + e.z * w2 + e.w * w3;
    }
    g_h[(size_t)(row0 + 0) * OUTF + c] = acc0;
    g_h[(size_t)(row0 + 1) * OUTF + c] = acc1;
    g_h[(size_t)(row0 + 2) * OUTF + c] = acc2;
    g_h[(size_t)(row0 + 3) * OUTF + c] = acc3;
}

// ---------------------------------------------------------------------------
// Kernel B: f_src[i] = h[i,:] . a[0:64] ; f_dst[i] = h[i,:] . a[64:128]
// one warp per row, 8 warps per block.
// ---------------------------------------------------------------------------
__global__ void __launch_bounds__(256) fsfd_kernel(const float* __restrict__ a) {
    int lane = threadIdx.x & 31;
    int row = blockIdx.x * 8 + (threadIdx.x >> 5);
    float h0 = g_h[(size_t)row * OUTF + lane];
    float h1 = g_h[(size_t)row * OUTF + lane + 32];
    float fs = h0 * a[lane] + h1 * a[lane + 32];
    float fd = h0 * a[64 + lane] + h1 * a[96 + lane];
    #pragma unroll
    for (int m = 16; m > 0; m >>= 1) {
        fs += __shfl_xor_sync(0xffffffffu, fs, m);
        fd += __shfl_xor_sync(0xffffffffu, fd, m);
    }
    if (lane == 0) {
        g_fs[row] = fs;
        g_fd[row] = fd;
    }
}

// ---------------------------------------------------------------------------
// Kernel C: fused masked-softmax + att@h + ELU.
// Block = 32 i-rows (TI), 256 threads. Loop over 64 chunks of CJ=128 j's.
//   stage 1: p[i][j] = adj ? exp(lrelu(s_i + d_j)) : 0   (+ running rowsum Z)
//   stage 2: acc[i][c] += p[i][j] * h[j][c]  (register-blocked tile GEMM)
// No max subtraction: lrelu bounds scores to ~[-15, 65] -> exp stays finite.
// ---------------------------------------------------------------------------
#define TI 32
#define CJ 128
#define P_PITCH 132   // pad to kill STS bank conflicts, keeps 8B alignment

__global__ void __launch_bounds__(256) attn_kernel(const int* __restrict__ adj,
                                                   float* __restrict__ out) {
    extern __shared__ float sm[];
    float* h_sh = sm;                       // CJ*OUTF      = 8192 floats
    float* p_sh = h_sh + CJ * OUTF;         // TI*P_PITCH   = 4224
    float* d_sh = p_sh + TI * P_PITCH;      // CJ           = 128
    float* s_sh = d_sh + CJ;                // TI           = 32
    float* z_sh = s_sh + TI;                // TI           = 32

    const int tid = threadIdx.x;
    const int i0 = blockIdx.x * TI;

    // stage-1 mapping: 8 threads per i-row
    const int p_i = tid >> 3;       // 0..31
    const int p_j0 = tid & 7;
    // stage-2 mapping: warp w owns rows r0..r0+3, lane owns cols 2*lane, 2*lane+1
    const int w = tid >> 5;
    const int lane = tid & 31;
    const int r0 = w * 4;

    if (tid < TI) {
        s_sh[tid] = g_fs[i0 + tid];
        z_sh[tid] = 0.f;
    }
    __syncthreads();
    const float s_i = s_sh[p_i];
    const int* adj_row = adj + (size_t)(i0 + p_i) * NN;

    float acc00 = 0.f, acc01 = 0.f, acc10 = 0.f, acc11 = 0.f;
    float acc20 = 0.f, acc21 = 0.f, acc30 = 0.f, acc31 = 0.f;

    for (int chunk = 0; chunk < NN / CJ; ++chunk) {
        const int j0 = chunk * CJ;

        // cooperative load of h chunk (2048 float4) + d chunk
        const float4* hsrc = (const float4*)(g_h + (size_t)j0 * OUTF);
        float4* hdst = (float4*)h_sh;
        #pragma unroll
        for (int t = 0; t < 8; ++t) {
            int idx = t * 256 + tid;
            hdst[idx] = hsrc[idx];
        }
        if (tid < CJ) d_sh[tid] = g_fd[j0 + tid];
        __syncthreads();

        // ---- stage 1: weights ----
        float zp = 0.f;
        #pragma unroll
        for (int it = 0; it < 16; ++it) {
            int jl = p_j0 + it * 8;
            int av = adj_row[j0 + jl];
            float t = s_i + d_sh[jl];
            float lr = fmaxf(t, ALPHA * t);       // leaky relu
            float wgt = (av > 0) ? __expf(lr) : 0.f;
            zp += wgt;
            p_sh[p_i * P_PITCH + jl] = wgt;
        }
        zp += __shfl_xor_sync(0xffffffffu, zp, 4);
        zp += __shfl_xor_sync(0xffffffffu, zp, 2);
        zp += __shfl_xor_sync(0xffffffffu, zp, 1);
        if ((tid & 7) == 0) z_sh[p_i] += zp;     // single owner thread per row
        __syncthreads();

        // ---- stage 2: acc += P_tile @ h_tile ----
        const float* hrow = h_sh + lane * 2;
        const float* prow0 = p_sh + (r0 + 0) * P_PITCH;
        const float* prow1 = p_sh + (r0 + 1) * P_PITCH;
        const float* prow2 = p_sh + (r0 + 2) * P_PITCH;
        const float* prow3 = p_sh + (r0 + 3) * P_PITCH;
        #pragma unroll 4
        for (int j = 0; j < CJ; j += 2) {
            float2 h0 = *(const float2*)(hrow + j * OUTF);
            float2 h1 = *(const float2*)(hrow + (j + 1) * OUTF);
            float2 q0 = *(const float2*)(prow0 + j);
            float2 q1 = *(const float2*)(prow1 + j);
            float2 q2 = *(const float2*)(prow2 + j);
            float2 q3 = *(const float2*)(prow3 + j);
            acc00 += q0.x * h0.x; acc00 += q0.y * h1.x;
            acc01 += q0.x * h0.y; acc01 += q0.y * h1.y;
            acc10 += q1.x * h0.x; acc10 += q1.y * h1.x;
            acc11 += q1.x * h0.y; acc11 += q1.y * h1.y;
            acc20 += q2.x * h0.x; acc20 += q2.y * h1.x;
            acc21 += q2.x * h0.y; acc21 += q2.y * h1.y;
            acc30 += q3.x * h0.x; acc30 += q3.y * h1.x;
            acc31 += q3.x * h0.y; acc31 += q3.y * h1.y;
        }
        __syncthreads();   // protect h_sh/p_sh before next chunk overwrite
    }

    // epilogue: normalize + ELU + store
    float accs[4][2] = {{acc00, acc01}, {acc10, acc11}, {acc20, acc21}, {acc30, acc31}};
    #pragma unroll
    for (int r = 0; r < 4; ++r) {
        float z = z_sh[r0 + r];
        float inv = 1.0f / z;
        float v0 = accs[r][0] * inv;
        float v1 = accs[r][1] * inv;
        v0 = (v0 > 0.f) ? v0 : expm1f(v0);
        v1 = (v1 > 0.f) ? v1 : expm1f(v1);
        float2 o = make_float2(v0, v1);
        *(float2*)&out[(size_t)(i0 + r0 + r) * OUTF + lane * 2] = o;
    }
}

// ---------------------------------------------------------------------------
extern "C" void kernel_launch(void* const* d_in, const int* in_sizes, int n_in,
                              void* d_out, int out_size) {
    const float* X = (const float*)d_in[0];   // [8192, 512] f32
    const int* adj = (const int*)d_in[1];     // [8192, 8192] i32
    const float* W = (const float*)d_in[2];   // [512, 64] f32
    const float* a = (const float*)d_in[3];   // [128, 1] f32
    float* out = (float*)d_out;               // [8192, 64] f32

    const int smem_bytes = (CJ * OUTF + TI * P_PITCH + CJ + TI + TI) * (int)sizeof(float);
    cudaFuncSetAttribute(attn_kernel, cudaFuncAttributeMaxDynamicSharedMemorySize, smem_bytes);

    gemm_h_kernel<<<NN / 16, 256>>>(X, W);
    fsfd_kernel<<<NN / 8, 256>>>(a);
    attn_kernel<<<NN / TI, 256, smem_bytes>>>(adj, out);
}

// round 4
// speedup vs baseline: 1.0004x; 1.0004x over previous
#include <cuda_runtime.h>
#include <cuda_bf16.h>

#define NN 8192
#define INF_DIM 512
#define OUTF 64
#define ALPHA 0.2f

#define NSLICE 8          // j-range split across blocks
#define TI 128            // i-rows per attn block
#define CJ 128            // j per chunk
#define P_PITCH 129       // 8*129 mod 32 = 8 -> 8-row stride hits distinct banks

typedef unsigned long long ull;

// scratch (no cudaMalloc allowed)
__device__ float g_h[NN * OUTF];                    // h = X @ W
__device__ float g_fs[NN];                          // f_src
__device__ float g_fd[NN];                          // f_dst
__device__ float g_accp[NSLICE * NN * OUTF];        // partial att@h per slice (16MB)
__device__ float g_zp[NSLICE * NN];                 // partial row sums per slice

// ---- packed f32x2 helpers ------------------------------------------------
__device__ __forceinline__ void ffma2(ull& d, ull a, ull b) {
    asm("fma.rn.f32x2 %0, %1, %2, %0;" : "+l"(d) : "l"(a), "l"(b));
}
__device__ __forceinline__ ull pack2(float x) {
    ull r;
    unsigned int u = __float_as_uint(x);
    asm("mov.b64 %0, {%1, %1};" : "=l"(r) : "r"(u));
    return r;
}

// ---------------------------------------------------------------------------
// Kernel A: h = X @ W.  Tiled smem GEMM with FFMA2.
// Block: 256 threads, 64 rows x 64 cols, K tiled by 64.
// thread tile: 4 rows x 4 cols (cols = cg*2+{0,1} and cg*2+32+{0,1})
// ---------------------------------------------------------------------------
__global__ void __launch_bounds__(256) gemm_h_kernel(const float* __restrict__ X,
                                                     const float* __restrict__ W) {
    __shared__ float w_sh[64 * 64];       // [k][c]
    __shared__ float x_sh[64 * 65];       // [k][r], pitch 65

    const int tid = threadIdx.x;
    const int i0 = blockIdx.x * 64;
    const int rg = tid >> 4;              // 16 rowgroups x 4 rows
    const int cg = tid & 15;              // 16 colgroups x (2+2) cols

    ull acc[4][2];
    #pragma unroll
    for (int r = 0; r < 4; ++r) { acc[r][0] = 0ull; acc[r][1] = 0ull; }

    const int xr = tid >> 2;              // row this thread loads (0..63)
    const int xk = (tid & 3) * 16;        // k offset within tile

    for (int kt = 0; kt < INF_DIM; kt += 64) {
        // W tile: rows kt..kt+63 all cols, contiguous 16KB
        const float4* wsrc = (const float4*)(W + (size_t)kt * OUTF);
        float4* wdst = (float4*)w_sh;
        #pragma unroll
        for (int t = 0; t < 4; ++t) wdst[t * 256 + tid] = wsrc[t * 256 + tid];

        // X tile, stored transposed [k][r]
        const float4* xsrc = (const float4*)(X + (size_t)(i0 + xr) * INF_DIM + kt + xk);
        #pragma unroll
        for (int t = 0; t < 4; ++t) {
            float4 v = xsrc[t];
            x_sh[(xk + t * 4 + 0) * 65 + xr] = v.x;
            x_sh[(xk + t * 4 + 1) * 65 + xr] = v.y;
            x_sh[(xk + t * 4 + 2) * 65 + xr] = v.z;
            x_sh[(xk + t * 4 + 3) * 65 + xr] = v.w;
        }
        __syncthreads();

        #pragma unroll 4
        for (int k = 0; k < 64; ++k) {
            ull w0 = *(const ull*)(w_sh + k * 64 + cg * 2);
            ull w1 = *(const ull*)(w_sh + k * 64 + cg * 2 + 32);
            const float* xp = x_sh + k * 65 + rg * 4;
            #pragma unroll
            for (int r = 0; r < 4; ++r) {
                ull xx = pack2(xp[r]);
                ffma2(acc[r][0], xx, w0);
                ffma2(acc[r][1], xx, w1);
            }
        }
        __syncthreads();
    }

    #pragma unroll
    for (int r = 0; r < 4; ++r) {
        float* dst = g_h + (size_t)(i0 + rg * 4 + r) * OUTF + cg * 2;
        *(ull*)(dst) = acc[r][0];
        *(ull*)(dst + 32) = acc[r][1];
    }
}

// ---------------------------------------------------------------------------
// Kernel B: f_src / f_dst.  One warp per row.
// ---------------------------------------------------------------------------
__global__ void __launch_bounds__(256) fsfd_kernel(const float* __restrict__ a) {
    int lane = threadIdx.x & 31;
    int row = blockIdx.x * 8 + (threadIdx.x >> 5);
    float h0 = g_h[(size_t)row * OUTF + lane];
    float h1 = g_h[(size_t)row * OUTF + lane + 32];
    float fs = h0 * a[lane] + h1 * a[lane + 32];
    float fd = h0 * a[64 + lane] + h1 * a[96 + lane];
    #pragma unroll
    for (int m = 16; m > 0; m >>= 1) {
        fs += __shfl_xor_sync(0xffffffffu, fs, m);
        fd += __shfl_xor_sync(0xffffffffu, fd, m);
    }
    if (lane == 0) { g_fs[row] = fs; g_fd[row] = fd; }
}

// ---------------------------------------------------------------------------
// Kernel C: fused masked-softmax weights + partial att@h.
// Block: 128 threads, TI=128 rows, one of NSLICE j-ranges (8 chunks of 128).
//   stage 1: warp w owns rows 32w..32w+31; lane = j; exp(lrelu(s+d)) masked by adj
//   stage 2: thread tile 8 rows x 8 cols, FFMA2, acc in regs
// No max subtraction needed: lrelu bounds scores so exp stays finite in fp32.
// ---------------------------------------------------------------------------
__global__ void __launch_bounds__(128) attn_kernel(const int* __restrict__ adj) {
    extern __shared__ float sm[];
    float* h_sh = sm;                        // CJ*OUTF = 8192
    float* p_sh = h_sh + CJ * OUTF;          // TI*P_PITCH = 16512
    float* d_sh = p_sh + TI * P_PITCH;       // CJ
    float* s_sh = d_sh + CJ;                 // TI
    float* z_sh = s_sh + TI;                 // TI

    const int tid = threadIdx.x;
    const int lane = tid & 31;
    const int w = tid >> 5;                  // warp 0..3
    const int i0 = blockIdx.x * TI;
    const int slice = blockIdx.y;
    const int chunk0 = slice * (NN / CJ / NSLICE);    // 8 chunks per slice
    const int nchunk = NN / CJ / NSLICE;

    // stage-2 mapping
    const int rg = tid >> 3;                 // 16 rowgroups x 8 rows
    const int cg = tid & 7;                  // 8 colgroups; cols cg*2 + 16t + {0,1}

    s_sh[tid] = g_fs[i0 + tid];
    z_sh[tid] = 0.f;
    __syncthreads();

    ull acc[8][4];
    #pragma unroll
    for (int r = 0; r < 8; ++r)
        #pragma unroll
        for (int t = 0; t < 4; ++t) acc[r][t] = 0ull;

    for (int ch = 0; ch < nchunk; ++ch) {
        const int j0 = (chunk0 + ch) * CJ;

        // cooperative load of h chunk (2048 float4) + d chunk
        const float4* hsrc = (const float4*)(g_h + (size_t)j0 * OUTF);
        float4* hdst = (float4*)h_sh;
        #pragma unroll
        for (int t = 0; t < 16; ++t) hdst[t * 128 + tid] = hsrc[t * 128 + tid];
        d_sh[tid] = g_fd[j0 + tid];
        __syncthreads();

        // ---- stage 1: attention weights -> p_sh ----
        {
            const size_t arow0 = (size_t)(i0 + w * 32) * NN + j0;
            #pragma unroll 2
            for (int r = 0; r < 32; ++r) {
                const int row = w * 32 + r;
                const float s_i = s_sh[row];
                const int* ap = adj + arow0 + (size_t)r * NN;
                float zp = 0.f;
                #pragma unroll
                for (int t = 0; t < 4; ++t) {
                    int j = t * 32 + lane;
                    int av = ap[j];
                    float v = s_i + d_sh[j];
                    float lr = fmaxf(v, ALPHA * v);
                    float wgt = (av > 0) ? __expf(lr) : 0.f;
                    p_sh[row * P_PITCH + j] = wgt;
                    zp += wgt;
                }
                #pragma unroll
                for (int m = 16; m > 0; m >>= 1)
                    zp += __shfl_xor_sync(0xffffffffu, zp, m);
                if (lane == 0) z_sh[row] += zp;
            }
        }
        __syncthreads();

        // ---- stage 2: acc += P_tile @ h_tile (FFMA2) ----
        {
            const float* hbase = h_sh + cg * 2;
            const float* pbase = p_sh + rg * 8 * P_PITCH;
            #pragma unroll 2
            for (int j = 0; j < CJ; ++j) {
                const float* hj = hbase + j * OUTF;
                ull h0 = *(const ull*)(hj);
                ull h1 = *(const ull*)(hj + 16);
                ull h2 = *(const ull*)(hj + 32);
                ull h3 = *(const ull*)(hj + 48);
                const float* pj = pbase + j;
                #pragma unroll
                for (int r = 0; r < 8; ++r) {
                    ull pp = pack2(pj[r * P_PITCH]);
                    ffma2(acc[r][0], pp, h0);
                    ffma2(acc[r][1], pp, h1);
                    ffma2(acc[r][2], pp, h2);
                    ffma2(acc[r][3], pp, h3);
                }
            }
        }
        __syncthreads();
    }

    // write partials
    #pragma unroll
    for (int r = 0; r < 8; ++r) {
        float* dst = g_accp + (size_t)slice * NN * OUTF
                   + (size_t)(i0 + rg * 8 + r) * OUTF + cg * 2;
        *(ull*)(dst +  0) = acc[r][0];
        *(ull*)(dst + 16) = acc[r][1];
        *(ull*)(dst + 32) = acc[r][2];
        *(ull*)(dst + 48) = acc[r][3];
    }
    g_zp[(size_t)slice * NN + i0 + tid] = z_sh[tid];
}

// ---------------------------------------------------------------------------
// Kernel D: combine slices, normalize, ELU, store.
// ---------------------------------------------------------------------------
__global__ void __launch_bounds__(256) combine_kernel(float* __restrict__ out) {
    int idx = blockIdx.x * 256 + threadIdx.x;
    int i = idx >> 6;
    float s = 0.f, z = 0.f;
    #pragma unroll
    for (int k = 0; k < NSLICE; ++k) {
        s += g_accp[(size_t)k * NN * OUTF + idx];
        z += g_zp[(size_t)k * NN + i];
    }
    float v = s / z;
    v = (v > 0.f) ? v : expm1f(v);
    out[idx] = v;
}

// ---------------------------------------------------------------------------
extern "C" void kernel_launch(void* const* d_in, const int* in_sizes, int n_in,
                              void* d_out, int out_size) {
    const float* X = (const float*)d_in[0];   // [8192, 512] f32
    const int* adj = (const int*)d_in[1];     // [8192, 8192] i32
    const float* W = (const float*)d_in[2];   // [512, 64] f32
    const float* a = (const float*)d_in[3];   // [128, 1] f32
    float* out = (float*)d_out;               // [8192, 64] f32

    const int attn_smem = (CJ * OUTF + TI * P_PITCH + CJ + TI + TI) * (int)sizeof(float);
    cudaFuncSetAttribute(attn_kernel, cudaFuncAttributeMaxDynamicSharedMemorySize, attn_smem);

    gemm_h_kernel<<<NN / 64, 256>>>(X, W);
    fsfd_kernel<<<NN / 8, 256>>>(a);
    attn_kernel<<<dim3(NN / TI, NSLICE), 128, attn_smem>>>(adj);
    combine_kernel<<<NN * OUTF / 256, 256>>>(out);
}

// round 5
// speedup vs baseline: 1.0168x; 1.0165x over previous
#include <cuda_runtime.h>
#include <cuda_bf16.h>

#define NN 8192
#define INF_DIM 512
#define OUTF 64
#define ALPHA 0.2f

#define NSLICE 8          // j-range split across blocks
#define TI 128            // i-rows per attn block
#define CJ 128            // j per chunk
#define P_PITCH 129       // 8*129 mod 32 = 8 -> 8-row stride hits distinct banks

typedef unsigned long long ull;

// scratch (no cudaMalloc allowed)
__device__ float g_h[NN * OUTF];                    // h = X @ W
__device__ float g_fs[NN];                          // f_src (s_i)
__device__ float g_R[NN];                           // exp(0.8 * s_i)
__device__ float g_ed[NN];                          // exp(d_j)
__device__ float g_ed5[NN];                         // exp(0.2 * d_j)
__device__ float g_fd[NN];                          // f_dst (d_j)
__device__ float g_accp[NSLICE * NN * OUTF];        // partial att@h per slice (16MB)
__device__ float g_zp[NSLICE * NN];                 // partial row sums per slice

// ---- packed f32x2 helpers ------------------------------------------------
__device__ __forceinline__ void ffma2(ull& d, ull a, ull b) {
    asm("fma.rn.f32x2 %0, %1, %2, %0;" : "+l"(d) : "l"(a), "l"(b));
}
__device__ __forceinline__ ull pack2(float x) {
    ull r;
    unsigned int u = __float_as_uint(x);
    asm("mov.b64 %0, {%1, %1};" : "=l"(r) : "r"(u));
    return r;
}

// ---------------------------------------------------------------------------
// Kernel A: h = X @ W.  Tiled smem GEMM with FFMA2.
// ---------------------------------------------------------------------------
__global__ void __launch_bounds__(256) gemm_h_kernel(const float* __restrict__ X,
                                                     const float* __restrict__ W) {
    __shared__ float w_sh[64 * 64];       // [k][c]
    __shared__ float x_sh[64 * 65];       // [k][r], pitch 65

    const int tid = threadIdx.x;
    const int i0 = blockIdx.x * 64;
    const int rg = tid >> 4;              // 16 rowgroups x 4 rows
    const int cg = tid & 15;              // 16 colgroups x (2+2) cols

    ull acc[4][2];
    #pragma unroll
    for (int r = 0; r < 4; ++r) { acc[r][0] = 0ull; acc[r][1] = 0ull; }

    const int xr = tid >> 2;              // row this thread loads (0..63)
    const int xk = (tid & 3) * 16;        // k offset within tile

    for (int kt = 0; kt < INF_DIM; kt += 64) {
        const float4* wsrc = (const float4*)(W + (size_t)kt * OUTF);
        float4* wdst = (float4*)w_sh;
        #pragma unroll
        for (int t = 0; t < 4; ++t) wdst[t * 256 + tid] = wsrc[t * 256 + tid];

        const float4* xsrc = (const float4*)(X + (size_t)(i0 + xr) * INF_DIM + kt + xk);
        #pragma unroll
        for (int t = 0; t < 4; ++t) {
            float4 v = xsrc[t];
            x_sh[(xk + t * 4 + 0) * 65 + xr] = v.x;
            x_sh[(xk + t * 4 + 1) * 65 + xr] = v.y;
            x_sh[(xk + t * 4 + 2) * 65 + xr] = v.z;
            x_sh[(xk + t * 4 + 3) * 65 + xr] = v.w;
        }
        __syncthreads();

        #pragma unroll 4
        for (int k = 0; k < 64; ++k) {
            ull w0 = *(const ull*)(w_sh + k * 64 + cg * 2);
            ull w1 = *(const ull*)(w_sh + k * 64 + cg * 2 + 32);
            const float* xp = x_sh + k * 65 + rg * 4;
            #pragma unroll
            for (int r = 0; r < 4; ++r) {
                ull xx = pack2(xp[r]);
                ffma2(acc[r][0], xx, w0);
                ffma2(acc[r][1], xx, w1);
            }
        }
        __syncthreads();
    }

    #pragma unroll
    for (int r = 0; r < 4; ++r) {
        float* dst = g_h + (size_t)(i0 + rg * 4 + r) * OUTF + cg * 2;
        *(ull*)(dst) = acc[r][0];
        *(ull*)(dst + 32) = acc[r][1];
    }
}

// ---------------------------------------------------------------------------
// Kernel B: f_src / f_dst + the factorized-exp node terms.
//   R_i   = exp(0.8 * s_i)       (row constant, pos branch)
//   Ed_j  = exp(d_j)             (pos branch)
//   Ed5_j = exp(0.2 * d_j)       (neg branch)
// Row i's weights are all scaled by 1/exp(0.2 s_i) -> cancels in softmax.
// ---------------------------------------------------------------------------
__global__ void __launch_bounds__(256) fsfd_kernel(const float* __restrict__ a) {
    int lane = threadIdx.x & 31;
    int row = blockIdx.x * 8 + (threadIdx.x >> 5);
    float h0 = g_h[(size_t)row * OUTF + lane];
    float h1 = g_h[(size_t)row * OUTF + lane + 32];
    float fs = h0 * a[lane] + h1 * a[lane + 32];
    float fd = h0 * a[64 + lane] + h1 * a[96 + lane];
    #pragma unroll
    for (int m = 16; m > 0; m >>= 1) {
        fs += __shfl_xor_sync(0xffffffffu, fs, m);
        fd += __shfl_xor_sync(0xffffffffu, fd, m);
    }
    if (lane == 0) {
        g_fs[row] = fs;
        g_fd[row] = fd;
        g_R[row] = __expf(0.8f * fs);
        g_ed[row] = __expf(fd);
        g_ed5[row] = __expf(ALPHA * fd);
    }
}

// ---------------------------------------------------------------------------
// Kernel C: fused masked-softmax weights (no MUFU in inner loop) + partial att@h.
// Block: 128 threads, TI=128 rows, one of NSLICE j-ranges (8 chunks of 128).
//   stage 1: warp w owns rows 32w..32w+31; lane = j mod 32
//            wgt = adj ? (s_i+d_j >= 0 ? R_i*Ed_j : Ed5_j) : 0
//   stage 2: thread tile 8 rows x 8 cols, FFMA2, acc in regs
// ---------------------------------------------------------------------------
__global__ void __launch_bounds__(128) attn_kernel(const int* __restrict__ adj) {
    extern __shared__ float sm[];
    float* h_sh = sm;                        // CJ*OUTF = 8192
    float* p_sh = h_sh + CJ * OUTF;          // TI*P_PITCH = 16512
    float* d_sh = p_sh + TI * P_PITCH;       // CJ
    float* ed_sh = d_sh + CJ;                // CJ
    float* ed5_sh = ed_sh + CJ;              // CJ
    float* s_sh = ed5_sh + CJ;               // TI
    float* r_sh = s_sh + TI;                 // TI
    float* z_sh = r_sh + TI;                 // TI

    const int tid = threadIdx.x;
    const int lane = tid & 31;
    const int w = tid >> 5;                  // warp 0..3
    const int i0 = blockIdx.x * TI;
    const int slice = blockIdx.y;
    const int nchunk = NN / CJ / NSLICE;     // 8
    const int chunk0 = slice * nchunk;

    // stage-2 mapping
    const int rg = tid >> 3;                 // 16 rowgroups x 8 rows
    const int cg = tid & 7;                  // 8 colgroups; cols cg*2 + 16t + {0,1}

    s_sh[tid] = g_fs[i0 + tid];
    r_sh[tid] = g_R[i0 + tid];
    z_sh[tid] = 0.f;
    __syncthreads();

    ull acc[8][4];
    #pragma unroll
    for (int r = 0; r < 8; ++r)
        #pragma unroll
        for (int t = 0; t < 4; ++t) acc[r][t] = 0ull;

    for (int ch = 0; ch < nchunk; ++ch) {
        const int j0 = (chunk0 + ch) * CJ;

        // cooperative load of h chunk (2048 float4) + node terms
        const float4* hsrc = (const float4*)(g_h + (size_t)j0 * OUTF);
        float4* hdst = (float4*)h_sh;
        #pragma unroll
        for (int t = 0; t < 16; ++t) hdst[t * 128 + tid] = hsrc[t * 128 + tid];
        d_sh[tid] = g_fd[j0 + tid];
        ed_sh[tid] = g_ed[j0 + tid];
        ed5_sh[tid] = g_ed5[j0 + tid];
        __syncthreads();

        // ---- stage 1: attention weights -> p_sh (ALU/FMA only) ----
        {
            const size_t arow0 = (size_t)(i0 + w * 32) * NN + j0;
            #pragma unroll 2
            for (int r = 0; r < 32; ++r) {
                const int row = w * 32 + r;
                const float s_i = s_sh[row];
                const float R_i = r_sh[row];
                const int* ap = adj + arow0 + (size_t)r * NN;
                float zp = 0.f;
                #pragma unroll
                for (int t = 0; t < 4; ++t) {
                    int j = t * 32 + lane;
                    int av = ap[j];
                    float v = s_i + d_sh[j];
                    float pos = R_i * ed_sh[j];
                    float sel = (v >= 0.f) ? pos : ed5_sh[j];
                    float wgt = (av > 0) ? sel : 0.f;
                    p_sh[row * P_PITCH + j] = wgt;
                    zp += wgt;
                }
                #pragma unroll
                for (int m = 16; m > 0; m >>= 1)
                    zp += __shfl_xor_sync(0xffffffffu, zp, m);
                if (lane == 0) z_sh[row] += zp;
            }
        }
        __syncthreads();

        // ---- stage 2: acc += P_tile @ h_tile (FFMA2) ----
        {
            const float* hbase = h_sh + cg * 2;
            const float* pbase = p_sh + rg * 8 * P_PITCH;
            #pragma unroll 2
            for (int j = 0; j < CJ; ++j) {
                const float* hj = hbase + j * OUTF;
                ull h0 = *(const ull*)(hj);
                ull h1 = *(const ull*)(hj + 16);
                ull h2 = *(const ull*)(hj + 32);
                ull h3 = *(const ull*)(hj + 48);
                const float* pj = pbase + j;
                #pragma unroll
                for (int r = 0; r < 8; ++r) {
                    ull pp = pack2(pj[r * P_PITCH]);
                    ffma2(acc[r][0], pp, h0);
                    ffma2(acc[r][1], pp, h1);
                    ffma2(acc[r][2], pp, h2);
                    ffma2(acc[r][3], pp, h3);
                }
            }
        }
        __syncthreads();
    }

    // write partials
    #pragma unroll
    for (int r = 0; r < 8; ++r) {
        float* dst = g_accp + (size_t)slice * NN * OUTF
                   + (size_t)(i0 + rg * 8 + r) * OUTF + cg * 2;
        *(ull*)(dst +  0) = acc[r][0];
        *(ull*)(dst + 16) = acc[r][1];
        *(ull*)(dst + 32) = acc[r][2];
        *(ull*)(dst + 48) = acc[r][3];
    }
    g_zp[(size_t)slice * NN + i0 + tid] = z_sh[tid];
}

// ---------------------------------------------------------------------------
// Kernel D: combine slices, normalize, ELU, store.
// ---------------------------------------------------------------------------
__global__ void __launch_bounds__(256) combine_kernel(float* __restrict__ out) {
    int idx = blockIdx.x * 256 + threadIdx.x;
    int i = idx >> 6;
    float s = 0.f, z = 0.f;
    #pragma unroll
    for (int k = 0; k < NSLICE; ++k) {
        s += g_accp[(size_t)k * NN * OUTF + idx];
        z += g_zp[(size_t)k * NN + i];
    }
    float v = s / z;
    v = (v > 0.f) ? v : expm1f(v);
    out[idx] = v;
}

// ---------------------------------------------------------------------------
extern "C" void kernel_launch(void* const* d_in, const int* in_sizes, int n_in,
                              void* d_out, int out_size) {
    const float* X = (const float*)d_in[0];   // [8192, 512] f32
    const int* adj = (const int*)d_in[1];     // [8192, 8192] i32
    const float* W = (const float*)d_in[2];   // [512, 64] f32
    const float* a = (const float*)d_in[3];   // [128, 1] f32
    float* out = (float*)d_out;               // [8192, 64] f32

    const int attn_smem = (CJ * OUTF + TI * P_PITCH + 3 * CJ + 3 * TI) * (int)sizeof(float);
    cudaFuncSetAttribute(attn_kernel, cudaFuncAttributeMaxDynamicSharedMemorySize, attn_smem);

    gemm_h_kernel<<<NN / 64, 256>>>(X, W);
    fsfd_kernel<<<NN / 8, 256>>>(a);
    attn_kernel<<<dim3(NN / TI, NSLICE), 128, attn_smem>>>(adj);
    combine_kernel<<<NN * OUTF / 256, 256>>>(out);
}

// round 9
// speedup vs baseline: 1.8134x; 1.7833x over previous
#include <cuda_runtime.h>
#include <cuda_bf16.h>
#include <cstdint>

#define NN 8192
#define INF_DIM 512
#define OUTF 64
#define ALPHA 0.2f

#define NSLICE 4
#define TI 64                     // i-rows per attn block
#define CJ 64                     // j per chunk
#define SLICE_J (NN / NSLICE)     // 2048
#define NCHUNK (SLICE_J / CJ)     // 32
#define P_PITCH 68                // p[j][row] pitch: 16B-aligned rows, conflict-free

typedef unsigned long long ull;

// ---------------- device scratch (no cudaMalloc allowed) -------------------
__device__ float g_h[NN * OUTF];                 // h = X @ W
__device__ float g_fs[NN];                       // s_i
__device__ float g_fd[NN];                       // d_j
__device__ float g_R[NN];                        // exp(0.8 s_i)
__device__ float g_ed[NN];                       // exp(d_j)
__device__ float g_ed5[NN];                      // exp(0.2 d_j)
__device__ float g_accD[NSLICE * NN * OUTF];     // partial att@h per slice
__device__ float g_accZ[NSLICE * NN];            // partial row sums per slice

// ---- packed f32x2 helpers ------------------------------------------------
__device__ __forceinline__ void ffma2(ull& d, ull a, ull b) {
    asm("fma.rn.f32x2 %0, %1, %2, %0;" : "+l"(d) : "l"(a), "l"(b));
}
__device__ __forceinline__ ull pack2(float x) {
    ull r; unsigned int u = __float_as_uint(x);
    asm("mov.b64 %0, {%1, %1};" : "=l"(r) : "r"(u));
    return r;
}

// ---------------------------------------------------------------------------
// Kernel A: h = X @ W.  Tiled smem GEMM with FFMA2 (verified R4/R5).
// ---------------------------------------------------------------------------
__global__ void __launch_bounds__(256) gemm_h_kernel(const float* __restrict__ X,
                                                     const float* __restrict__ W) {
    __shared__ float w_sh[64 * 64];
    __shared__ float x_sh[64 * 65];

    const int tid = threadIdx.x;
    const int i0 = blockIdx.x * 64;
    const int rg = tid >> 4;
    const int cg = tid & 15;

    ull acc[4][2];
    #pragma unroll
    for (int r = 0; r < 4; ++r) { acc[r][0] = 0ull; acc[r][1] = 0ull; }

    const int xr = tid >> 2;
    const int xk = (tid & 3) * 16;

    for (int kt = 0; kt < INF_DIM; kt += 64) {
        const float4* wsrc = (const float4*)(W + (size_t)kt * OUTF);
        float4* wdst = (float4*)w_sh;
        #pragma unroll
        for (int t = 0; t < 4; ++t) wdst[t * 256 + tid] = wsrc[t * 256 + tid];

        const float4* xsrc = (const float4*)(X + (size_t)(i0 + xr) * INF_DIM + kt + xk);
        #pragma unroll
        for (int t = 0; t < 4; ++t) {
            float4 v = xsrc[t];
            x_sh[(xk + t * 4 + 0) * 65 + xr] = v.x;
            x_sh[(xk + t * 4 + 1) * 65 + xr] = v.y;
            x_sh[(xk + t * 4 + 2) * 65 + xr] = v.z;
            x_sh[(xk + t * 4 + 3) * 65 + xr] = v.w;
        }
        __syncthreads();

        #pragma unroll 4
        for (int k = 0; k < 64; ++k) {
            ull w0 = *(const ull*)(w_sh + k * 64 + cg * 2);
            ull w1 = *(const ull*)(w_sh + k * 64 + cg * 2 + 32);
            const float* xp = x_sh + k * 65 + rg * 4;
            #pragma unroll
            for (int r = 0; r < 4; ++r) {
                ull xx = pack2(xp[r]);
                ffma2(acc[r][0], xx, w0);
                ffma2(acc[r][1], xx, w1);
            }
        }
        __syncthreads();
    }

    #pragma unroll
    for (int r = 0; r < 4; ++r) {
        float* dst = g_h + (size_t)(i0 + rg * 4 + r) * OUTF + cg * 2;
        *(ull*)(dst) = acc[r][0];
        *(ull*)(dst + 32) = acc[r][1];
    }
}

// ---------------------------------------------------------------------------
// Kernel B: f_src/f_dst + factorized exp node terms (verified R5).
//   wgt_ij = adj * ( s_i+d_j >= 0 ? exp(0.8 s_i)*exp(d_j) : exp(0.2 d_j) )
//   (row i scaled by 1/exp(0.2 s_i) -> cancels in softmax)
// ---------------------------------------------------------------------------
__global__ void __launch_bounds__(256) fsfd_kernel(const float* __restrict__ a) {
    int lane = threadIdx.x & 31;
    int row = blockIdx.x * 8 + (threadIdx.x >> 5);
    float h0 = g_h[(size_t)row * OUTF + lane];
    float h1 = g_h[(size_t)row * OUTF + lane + 32];
    float fs = h0 * a[lane] + h1 * a[lane + 32];
    float fd = h0 * a[64 + lane] + h1 * a[96 + lane];
    #pragma unroll
    for (int m = 16; m > 0; m >>= 1) {
        fs += __shfl_xor_sync(0xffffffffu, fs, m);
        fd += __shfl_xor_sync(0xffffffffu, fd, m);
    }
    if (lane == 0) {
        g_fs[row] = fs;
        g_fd[row] = fd;
        g_R[row] = __expf(0.8f * fs);
        g_ed[row] = __expf(fd);
        g_ed5[row] = __expf(ALPHA * fd);
    }
}

// ---------------------------------------------------------------------------
// Kernel C: fused attn.  128 threads, TI=64 rows, CJ=64-j chunks, NSLICE=4.
//   stage 1: thread (row = tid&63, half = tid>>6) computes 32 weights
//            -> p_sh TRANSPOSED [j][row] (pitch 68), z in registers.
//   stage 2: thread (rg = tid>>3, cg = tid&7): 4 rows x 8 cols, FFMA2;
//            p via LDS.128 (4 rows at once), h via LDS.64 — conflict-free.
// ~35KB static smem -> count-limited occupancy ~14 warps/SM.
// ---------------------------------------------------------------------------
__global__ void __launch_bounds__(128) attn_kernel(const int* __restrict__ adj) {
    __shared__ float h_sh[CJ * OUTF];        // 16KB  [j][c]
    __shared__ float p_sh[CJ * P_PITCH];     // 17.4KB [j][row]
    __shared__ float4 tab[CJ];               // (d_j, ed_j, ed5_j, 0)
    __shared__ float z_part[128];

    const int tid = threadIdx.x;
    const int i0 = blockIdx.x * TI;
    const int slice = blockIdx.y;
    const int jbase = slice * SLICE_J;

    // stage-1 identity
    const int row = tid & 63;
    const int half = tid >> 6;
    const float s_i = g_fs[i0 + row];
    const float R_i = g_R[i0 + row];
    float z_acc = 0.f;

    // stage-2 identity
    const int rg = tid >> 3;                 // 16 rowgroups x 4 rows
    const int cg = tid & 7;                  // cols cg*2 + 16t + {0,1}

    ull acc[4][4];
    #pragma unroll
    for (int r = 0; r < 4; ++r)
        #pragma unroll
        for (int t = 0; t < 4; ++t) acc[r][t] = 0ull;

    for (int ch = 0; ch < NCHUNK; ++ch) {
        const int j0 = jbase + ch * CJ;

        // ---- load h tile + node-term table ----
        {
            const float4* hsrc = (const float4*)(g_h + (size_t)j0 * OUTF);
            float4* hdst = (float4*)h_sh;
            #pragma unroll
            for (int t = 0; t < 8; ++t) hdst[t * 128 + tid] = hsrc[t * 128 + tid];
            if (tid < CJ)
                tab[tid] = make_float4(g_fd[j0 + tid], g_ed[j0 + tid], g_ed5[j0 + tid], 0.f);
        }
        __syncthreads();

        // ---- stage 1: weights -> p_sh[j][row] ----
        {
            const int4* ap = (const int4*)(adj + (size_t)(i0 + row) * NN + j0 + half * 32);
            float zc = 0.f;
            #pragma unroll
            for (int t = 0; t < 8; ++t) {
                int4 av = ap[t];
                const int jb = half * 32 + t * 4;
                float4 b0 = tab[jb + 0];
                float4 b1 = tab[jb + 1];
                float4 b2 = tab[jb + 2];
                float4 b3 = tab[jb + 3];
                float sel0 = (s_i + b0.x >= 0.f) ? R_i * b0.y : b0.z;
                float sel1 = (s_i + b1.x >= 0.f) ? R_i * b1.y : b1.z;
                float sel2 = (s_i + b2.x >= 0.f) ? R_i * b2.y : b2.z;
                float sel3 = (s_i + b3.x >= 0.f) ? R_i * b3.y : b3.z;
                float w0 = (av.x != 0) ? sel0 : 0.f;
                float w1 = (av.y != 0) ? sel1 : 0.f;
                float w2 = (av.z != 0) ? sel2 : 0.f;
                float w3 = (av.w != 0) ? sel3 : 0.f;
                p_sh[(jb + 0) * P_PITCH + row] = w0;
                p_sh[(jb + 1) * P_PITCH + row] = w1;
                p_sh[(jb + 2) * P_PITCH + row] = w2;
                p_sh[(jb + 3) * P_PITCH + row] = w3;
                zc += (w0 + w1) + (w2 + w3);
            }
            z_acc += zc;
        }
        __syncthreads();

        // ---- stage 2: acc += P^T tile x h tile (FFMA2) ----
        {
            const float* hbase = h_sh + cg * 2;
            const float* pbase = p_sh + rg * 4;
            #pragma unroll 8
            for (int j = 0; j < CJ; ++j) {
                float4 pv = *(const float4*)(pbase + j * P_PITCH);
                const float* hj = hbase + j * OUTF;
                ull h0 = *(const ull*)(hj);
                ull h1 = *(const ull*)(hj + 16);
                ull h2 = *(const ull*)(hj + 32);
                ull h3 = *(const ull*)(hj + 48);
                ull p0 = pack2(pv.x);
                ull p1 = pack2(pv.y);
                ull p2 = pack2(pv.z);
                ull p3 = pack2(pv.w);
                ffma2(acc[0][0], p0, h0); ffma2(acc[0][1], p0, h1);
                ffma2(acc[0][2], p0, h2); ffma2(acc[0][3], p0, h3);
                ffma2(acc[1][0], p1, h0); ffma2(acc[1][1], p1, h1);
                ffma2(acc[1][2], p1, h2); ffma2(acc[1][3], p1, h3);
                ffma2(acc[2][0], p2, h0); ffma2(acc[2][1], p2, h1);
                ffma2(acc[2][2], p2, h2); ffma2(acc[2][3], p2, h3);
                ffma2(acc[3][0], p3, h0); ffma2(acc[3][1], p3, h1);
                ffma2(acc[3][2], p3, h2); ffma2(acc[3][3], p3, h3);
            }
        }
        __syncthreads();
    }

    // ---- epilogue ----
    #pragma unroll
    for (int r = 0; r < 4; ++r) {
        float* dst = g_accD + ((size_t)slice * NN + i0 + rg * 4 + r) * OUTF + cg * 2;
        *(ull*)(dst +  0) = acc[r][0];
        *(ull*)(dst + 16) = acc[r][1];
        *(ull*)(dst + 32) = acc[r][2];
        *(ull*)(dst + 48) = acc[r][3];
    }
    z_part[tid] = z_acc;
    __syncthreads();
    if (tid < TI)
        g_accZ[(size_t)slice * NN + i0 + tid] = z_part[tid] + z_part[tid + 64];
}

// ---------------------------------------------------------------------------
// Kernel D: combine slices, normalize, ELU, store.
// ---------------------------------------------------------------------------
__global__ void __launch_bounds__(256) combine_kernel(float* __restrict__ out) {
    int idx = blockIdx.x * 256 + threadIdx.x;
    int i = idx >> 6;
    float s = 0.f, z = 0.f;
    #pragma unroll
    for (int k = 0; k < NSLICE; ++k) {
        s += g_accD[(size_t)k * NN * OUTF + idx];
        z += g_accZ[(size_t)k * NN + i];
    }
    float v = s / z;
    v = (v > 0.f) ? v : expm1f(v);
    out[idx] = v;
}

// ---------------------------------------------------------------------------
extern "C" void kernel_launch(void* const* d_in, const int* in_sizes, int n_in,
                              void* d_out, int out_size) {
    const float* X = (const float*)d_in[0];   // [8192, 512] f32
    const int* adj = (const int*)d_in[1];     // [8192, 8192] i32
    const float* W = (const float*)d_in[2];   // [512, 64] f32
    const float* a = (const float*)d_in[3];   // [128, 1] f32
    float* out = (float*)d_out;               // [8192, 64] f32

    gemm_h_kernel<<<NN / 64, 256>>>(X, W);
    fsfd_kernel<<<NN / 8, 256>>>(a);
    attn_kernel<<<dim3(NN / TI, NSLICE), 128>>>(adj);
    combine_kernel<<<NN * OUTF / 256, 256>>>(out);
}